// round 1
// baseline (speedup 1.0000x reference)
#include <cuda_runtime.h>
#include <cuda_bf16.h>

// Problem constants (from reference):
//   HW = [(68,120),(34,60),(17,30)], STRIDES = [8,16,32]
//   A = 8160 + 2040 + 510 = 10710, B = 32, G = 50, CH = 16
// Output layout (flattened concat of the reference tuple, all float32):
//   [0, B*A*16)                      decoded
//   [B*A*16, B*A*16 + B*A)           fg_mask (0/1)
//   [B*A*16 + B*A, ... + B*G*A)      in_box_and_ctr (0/1), layout (B, G, A)

#define A_TOTAL 10710
#define A_L0    8160    // 68*120, stride 8
#define A_L01   10200   // + 34*60, stride 16
#define NB      32
#define NG      50
#define NCH     16
#define CENTER_RADIUS 2.5f

__device__ __forceinline__ void anchor_info(int a, float& xg, float& yg, float& s) {
    int i, w;
    if (a < A_L0)       { i = a;          w = 120; s = 8.0f;  }
    else if (a < A_L01) { i = a - A_L0;   w = 60;  s = 16.0f; }
    else                { i = a - A_L01;  w = 30;  s = 32.0f; }
    yg = (float)(i / w);
    xg = (float)(i % w);
}

__global__ __launch_bounds__(256)
void fused_decode_mask_kernel(const float* __restrict__ preds,
                              const float* __restrict__ labels,
                              float* __restrict__ out) {
    __shared__ float sgx[NG], sgy[NG], shw[NG], shh[NG];
    __shared__ int   sval[NG];

    const int b   = blockIdx.y;
    const int tid = threadIdx.x;
    const int a   = blockIdx.x * blockDim.x + tid;

    // Load this batch's labels into shared (50 boxes x 5 floats)
    if (tid < NG) {
        const float* lb = labels + ((size_t)b * NG + tid) * 5;
        float c  = lb[0];
        float gx = lb[1];
        float gy = lb[2];
        float gw = lb[3];
        float gh = lb[4];
        sgx[tid] = gx;
        sgy[tid] = gy;
        shw[tid] = 0.5f * gw;
        shh[tid] = 0.5f * gh;
        // valid = sum(labels, axis=2) > 0   (left-to-right sum like jnp)
        sval[tid] = ((((c + gx) + gy) + gw) + gh) > 0.0f ? 1 : 0;
    }
    __syncthreads();

    if (a >= A_TOTAL) return;

    float xg, yg, s;
    anchor_info(a, xg, yg, s);

    // ---- decode: 16 channels, vectorized float4 x4 ----
    {
        const float4* p4 = reinterpret_cast<const float4*>(
            preds + ((size_t)b * A_TOTAL + a) * NCH);
        float4* o4 = reinterpret_cast<float4*>(
            out + ((size_t)b * A_TOTAL + a) * NCH);
        float4 v0 = p4[0];
        float4 v1 = p4[1];
        float4 v2 = p4[2];
        float4 v3 = p4[3];
        float4 r0;
        r0.x = (v0.x + xg) * s;
        r0.y = (v0.y + yg) * s;
        r0.z = expf(v0.z) * s;
        r0.w = expf(v0.w) * s;
        o4[0] = r0;
        o4[1] = v1;
        o4[2] = v2;
        o4[3] = v3;
    }

    // ---- masks ----
    const float xc = (xg + 0.5f) * s;
    const float yc = (yg + 0.5f) * s;
    const float r  = CENTER_RADIUS * s;

    unsigned long long box_bits = 0ull, ctr_bits = 0ull;

#pragma unroll
    for (int g = 0; g < NG; ++g) {
        const float gx = sgx[g];
        const float gy = sgy[g];
        const float hw = shw[g];
        const float hh = shh[g];

        // in_box: min of 4 signed distances > 0
        float mb = fminf(fminf(xc - (gx - hw), (gx + hw) - xc),
                         fminf(yc - (gy - hh), (gy + hh) - yc));
        // in_ctr: same with radius r
        float mc = fminf(fminf(xc - (gx - r), (gx + r) - xc),
                         fminf(yc - (gy - r), (gy + r) - yc));

        if (sval[g]) {
            if (mb > 0.0f) box_bits |= (1ull << g);
            if (mc > 0.0f) ctr_bits |= (1ull << g);
        }
    }

    const bool fg = (box_bits | ctr_bits) != 0ull;

    float* out_fg  = out + (size_t)NB * A_TOTAL * NCH;
    float* out_ibc = out_fg + (size_t)NB * A_TOTAL;

    out_fg[(size_t)b * A_TOTAL + a] = fg ? 1.0f : 0.0f;

    const unsigned long long both = fg ? (box_bits & ctr_bits) : 0ull;
    const size_t base = (size_t)b * NG * A_TOTAL + a;
#pragma unroll
    for (int g = 0; g < NG; ++g) {
        out_ibc[base + (size_t)g * A_TOTAL] =
            ((both >> g) & 1ull) ? 1.0f : 0.0f;
    }
}

extern "C" void kernel_launch(void* const* d_in, const int* in_sizes, int n_in,
                              void* d_out, int out_size) {
    const float* preds  = (const float*)d_in[0];
    const float* labels = (const float*)d_in[1];
    float* out = (float*)d_out;

    dim3 block(256);
    dim3 grid((A_TOTAL + 255) / 256, NB);
    fused_decode_mask_kernel<<<grid, block>>>(preds, labels, out);
}